// round 9
// baseline (speedup 1.0000x reference)
#include <cuda_runtime.h>
#include <math.h>

#define TOPK     64
#define NBINS    65536
#define NCHUNK   256
#define MAXCAND  4096
#define TPB      512          // 16 warps
#define NBLOCKS  148          // 1 per SM, persistent
#define DDIM     512
#define TILE_ROWS   16
#define STAGES      5
#define TILE_FLOATS (TILE_ROWS * DDIM)          // 8192 floats = 32 KB
#define TILE_F4     (TILE_FLOATS / 4)           // 2048 float4

__device__ float        g_alpha[262144];
__device__ unsigned int g_hist[NBINS];     // fkey >> 16 (fine hist ONLY)
__device__ unsigned int g_done;            // zero-init; reset each run

// order-preserving float -> uint key
__device__ __forceinline__ unsigned int fkey(float f) {
    unsigned int b = __float_as_uint(f);
    return (b & 0x80000000u) ? ~b : (b | 0x80000000u);
}

__device__ __forceinline__ void cp_async16(void* smem_dst, const void* gmem_src) {
    unsigned int s = (unsigned int)__cvta_generic_to_shared(smem_dst);
    asm volatile("cp.async.cg.shared.global [%0], [%1], 16;\n" :: "r"(s), "l"(gmem_src));
}
__device__ __forceinline__ void cp_commit() {
    asm volatile("cp.async.commit_group;\n" ::: "memory");
}
template <int Npend>
__device__ __forceinline__ void cp_wait() {
    asm volatile("cp.async.wait_group %0;\n" :: "n"(Npend) : "memory");
}

// dynamic smem: [0,2048) sv | [2048, 2048+STAGES*32768) tiles (tail aliases tiles)
#define SMEM_BYTES (2048 + STAGES * TILE_FLOATS * 4)

__global__ void __launch_bounds__(TPB, 1)
fused_kernel(const float* __restrict__ v,
             const float* __restrict__ vs,
             const float* __restrict__ scores,
             float* __restrict__ out, int N) {
    extern __shared__ char smem_raw[];
    float* sv  = (float*)smem_raw;
    float* buf = (float*)(smem_raw + 2048);

    const int tid  = threadIdx.x;
    const int lane = tid & 31;
    const int warp = tid >> 5;

    for (int i = tid; i < DDIM; i += TPB) sv[i] = v[i];
    __syncthreads();

    // v slice held in registers for the whole matvec (1 block/SM -> regs are cheap)
    const float4* vv4 = (const float4*)sv;
    const float4 y0 = vv4[lane +  0];
    const float4 y1 = vv4[lane + 32];
    const float4 y2 = vv4[lane + 64];
    const float4 y3 = vv4[lane + 96];

    const int ntiles  = (N + TILE_ROWS - 1) / TILE_ROWS;
    const int mytiles = (ntiles - blockIdx.x + gridDim.x - 1) / gridDim.x;
    const long long totF4 = (long long)N * (DDIM / 4);

    auto issue_tile = [&](int k) {
        if (k < mytiles) {
            int t = blockIdx.x + k * gridDim.x;
            float4*       dst = (float4*)(buf + (k % STAGES) * TILE_FLOATS);
            const float4* src = (const float4*)vs + (long long)t * TILE_F4;
            long long base = (long long)t * TILE_F4;
#pragma unroll
            for (int c = 0; c < 4; c++) {
                int j = tid + c * TPB;
                if (base + j < totF4) cp_async16(&dst[j], &src[j]);
            }
        }
        cp_commit();   // uniform group count on every thread
    };

    // prime the pipeline
#pragma unroll
    for (int k = 0; k < STAGES; k++) issue_tile(k);

    for (int k = 0; k < mytiles; k++) {
        cp_wait<STAGES - 1>();   // tile k resident
        __syncthreads();

        int t   = blockIdx.x + k * gridDim.x;
        int row = t * TILE_ROWS + warp;
        if (row < N) {
            const float4* bb = (const float4*)(buf + (k % STAGES) * TILE_FLOATS
                                               + warp * DDIM);
            float4 x0 = bb[lane +  0];
            float4 x1 = bb[lane + 32];
            float4 x2 = bb[lane + 64];
            float4 x3 = bb[lane + 96];
            float a0 = x0.x*y0.x + x0.y*y0.y + x0.z*y0.z + x0.w*y0.w;
            float a1 = x1.x*y1.x + x1.y*y1.y + x1.z*y1.z + x1.w*y1.w;
            float a2 = x2.x*y2.x + x2.y*y2.y + x2.z*y2.z + x2.w*y2.w;
            float a3 = x3.x*y3.x + x3.y*y3.y + x3.z*y3.z + x3.w*y3.w;
            float acc = (a0 + a1) + (a2 + a3);
#pragma unroll
            for (int o = 16; o; o >>= 1) acc += __shfl_xor_sync(0xffffffffu, acc, o);
            if (lane == 0) {
                g_alpha[row] = acc;
                atomicAdd(&g_hist[fkey(acc) >> 16], 1u);  // fine hist only
            }
        }
        __syncthreads();         // stage k%STAGES now reusable
        issue_tile(k + STAGES);
    }
    cp_wait<0>();

    // ---------------- last-block election ------------------------------------
    __shared__ unsigned int s_isLast;
    __threadfence();
    __syncthreads();
    if (tid == 0)
        s_isLast = (atomicAdd(&g_done, 1u) == gridDim.x - 1) ? 1u : 0u;
    __syncthreads();
    if (!s_isLast) return;
    __threadfence();

    // -------- phase 2: coarse sums from fine hist, then threshold bin --------
    __shared__ unsigned int sc[NCHUNK];
    {
        const uint4* h4 = (const uint4*)g_hist;
        unsigned int s = 0;
        int base = tid * 32;                      // 32 uint4 = 128 bins/thread
#pragma unroll 8
        for (int j = 0; j < 32; j++) {
            uint4 u = h4[base + j];
            s += u.x + u.y + u.z + u.w;
        }
        __shared__ unsigned int half[TPB];
        half[tid] = s;
        __syncthreads();
        if (tid < NCHUNK) sc[tid] = half[2 * tid] + half[2 * tid + 1];
        __syncthreads();
    }

    __shared__ int s_chunk;
    __shared__ unsigned int s_above;
    __shared__ unsigned int s_tb;
    if (tid == 0) {
        unsigned int cum = 0;
        int c;
        for (c = 255; c >= 0; c--) {
            if (cum + sc[c] >= (unsigned int)TOPK) break;
            cum += sc[c];
        }
        if (c < 0) c = 0;
        s_chunk = c;
        s_above = cum;
    }
    __syncthreads();
    __shared__ unsigned int sf[256];
    if (tid < 256) sf[tid] = g_hist[s_chunk * 256 + tid];
    __syncthreads();
    if (tid == 0) {
        unsigned int cum = s_above;
        int b;
        for (b = 255; b >= 0; b--) {
            cum += sf[b];
            if (cum >= (unsigned int)TOPK) break;
        }
        if (b < 0) b = 0;
        s_tb = (unsigned int)(s_chunk * 256 + b);
    }
    __syncthreads();
    unsigned int tb = s_tb;

    // -------- phase 3: scan alpha (L2-hot), candidates into smem -------------
    float* sval = buf;                      // alias tile buffers
    int*   sidx = (int*)(buf + MAXCAND);
    __shared__ int s_cand;
    if (tid == 0) s_cand = 0;
    __syncthreads();

    int n4 = N >> 2;
    for (int i = tid; i < n4; i += TPB) {
        float4 a = ((const float4*)g_alpha)[i];
        int base = i << 2;
        if ((fkey(a.x) >> 16) >= tb) {
            int p = atomicAdd(&s_cand, 1);
            if (p < MAXCAND) { sval[p] = a.x; sidx[p] = base + 0; }
        }
        if ((fkey(a.y) >> 16) >= tb) {
            int p = atomicAdd(&s_cand, 1);
            if (p < MAXCAND) { sval[p] = a.y; sidx[p] = base + 1; }
        }
        if ((fkey(a.z) >> 16) >= tb) {
            int p = atomicAdd(&s_cand, 1);
            if (p < MAXCAND) { sval[p] = a.z; sidx[p] = base + 2; }
        }
        if ((fkey(a.w) >> 16) >= tb) {
            int p = atomicAdd(&s_cand, 1);
            if (p < MAXCAND) { sval[p] = a.w; sidx[p] = base + 3; }
        }
    }
    if (tid == 0) {
        for (int i = n4 << 2; i < N; i++) {
            float a = g_alpha[i];
            if ((fkey(a) >> 16) >= tb) {
                int p = atomicAdd(&s_cand, 1);
                if (p < MAXCAND) { sval[p] = a; sidx[p] = i; }
            }
        }
    }
    __syncthreads();
    int C = s_cand;
    if (C > MAXCAND) C = MAXCAND;

    // -------- phase 4: max, rank-select, softmax, weighted sum ---------------
    __shared__ float r1[TPB];
    __shared__ float r2[TPB];

    float m = -INFINITY;
    for (int i = tid; i < C; i += TPB) m = fmaxf(m, sval[i]);
    r1[tid] = m;
    __syncthreads();
    for (int s = TPB / 2; s; s >>= 1) {
        if (tid < s) r1[tid] = fmaxf(r1[tid], r1[tid + s]);
        __syncthreads();
    }
    m = r1[0];
    __syncthreads();

    float se = 0.f, acc = 0.f;
    for (int i = tid; i < C; i += TPB) {
        float vi = sval[i];
        unsigned int ki = fkey(vi);
        int rank = 0;
        for (int j = 0; j < C; j++) {
            unsigned int kj = fkey(sval[j]);
            rank += (kj > ki) || (kj == ki && j < i);
        }
        if (rank < TOPK) {
            float e = __expf(vi - m);
            se += e;
            acc += e * scores[sidx[i]];
        }
    }
    r1[tid] = se;
    r2[tid] = acc;
    __syncthreads();
    for (int s = TPB / 2; s; s >>= 1) {
        if (tid < s) {
            r1[tid] += r1[tid + s];
            r2[tid] += r2[tid + s];
        }
        __syncthreads();
    }
    if (tid == 0) out[0] = r2[0] / r1[0];

    // -------- phase 5: selective reset for next graph replay -----------------
    if (tid < NCHUNK) {
        if (sc[tid] != 0u) {
            uint4 z = make_uint4(0u, 0u, 0u, 0u);
            uint4* dst = (uint4*)&g_hist[tid * 256];
#pragma unroll
            for (int j = 0; j < 64; j++) dst[j] = z;
        }
    }
    if (tid == 0) g_done = 0u;
}

// ---------------- launch ------------------------------------------------------
extern "C" void kernel_launch(void* const* d_in, const int* in_sizes, int n_in,
                              void* d_out, int out_size) {
    const float* v      = (const float*)d_in[0];
    const float* vs     = (const float*)d_in[1];
    const float* scores = (const float*)d_in[2];
    float* out = (float*)d_out;
    int N = in_sizes[2];
    (void)n_in; (void)out_size;

    cudaFuncSetAttribute(fused_kernel,
                         cudaFuncAttributeMaxDynamicSharedMemorySize, SMEM_BYTES);
    fused_kernel<<<NBLOCKS, TPB, SMEM_BYTES>>>(v, vs, scores, out, N);
}

// round 10
// speedup vs baseline: 1.0392x; 1.0392x over previous
#include <cuda_runtime.h>
#include <math.h>

#define TOPK     64
#define NBINS    65536
#define NCHUNK   256
#define MAXCAND  4096
#define TPB      512          // 16 warps
#define NBLOCKS  148          // 1 per SM, persistent
#define DDIM     512
#define TILE_ROWS   16
#define STAGES      5
#define TILE_FLOATS (TILE_ROWS * DDIM)          // 8192 floats = 32 KB
#define TILE_BYTES  (TILE_FLOATS * 4)

__device__ float        g_alpha[262144];
__device__ unsigned int g_hist[NBINS];     // fkey >> 16 (fine hist only)
__device__ unsigned int g_done;            // zero-init; reset each run

__device__ __forceinline__ unsigned int fkey(float f) {
    unsigned int b = __float_as_uint(f);
    return (b & 0x80000000u) ? ~b : (b | 0x80000000u);
}

__device__ __forceinline__ unsigned int smem_u32(const void* p) {
    return (unsigned int)__cvta_generic_to_shared(p);
}
__device__ __forceinline__ void mbar_init(unsigned int mbar, unsigned int count) {
    asm volatile("mbarrier.init.shared.b64 [%0], %1;" :: "r"(mbar), "r"(count) : "memory");
}
__device__ __forceinline__ void mbar_expect_tx(unsigned int mbar, unsigned int bytes) {
    asm volatile("mbarrier.arrive.expect_tx.shared.b64 _, [%0], %1;"
                 :: "r"(mbar), "r"(bytes) : "memory");
}
__device__ __forceinline__ void tma_bulk_1d(unsigned int dst_smem, const void* src,
                                            unsigned int bytes, unsigned int mbar) {
    asm volatile("cp.async.bulk.shared::cta.global.mbarrier::complete_tx::bytes "
                 "[%0], [%1], %2, [%3];"
                 :: "r"(dst_smem), "l"(src), "r"(bytes), "r"(mbar) : "memory");
}
__device__ __forceinline__ void mbar_wait(unsigned int mbar, unsigned int parity) {
    unsigned int done;
    asm volatile("{\n\t.reg .pred p;\n\t"
                 "mbarrier.try_wait.parity.acquire.cta.shared::cta.b64 p, [%1], %2;\n\t"
                 "selp.b32 %0, 1, 0, p;\n\t}"
                 : "=r"(done) : "r"(mbar), "r"(parity) : "memory");
    if (!done) {
        asm volatile("{\n\t.reg .pred P1;\n\t"
                     "WL_%=:\n\t"
                     "mbarrier.try_wait.parity.acquire.cta.shared::cta.b64 P1, [%0], %1, 0x989680;\n\t"
                     "@P1 bra.uni WD_%=;\n\t"
                     "bra.uni WL_%=;\n\t"
                     "WD_%=:\n\t}"
                     :: "r"(mbar), "r"(parity) : "memory");
    }
}

// dynamic smem: [0,2048) sv | [2048, 2048+64) mbarriers | [4096, ...) tile stages
#define SMEM_BYTES (4096 + STAGES * TILE_BYTES)

__global__ void __launch_bounds__(TPB, 1)
fused_kernel(const float* __restrict__ v,
             const float* __restrict__ vs,
             const float* __restrict__ scores,
             float* __restrict__ out, int N) {
    extern __shared__ char smem_raw[];
    float* sv  = (float*)smem_raw;
    unsigned long long* mbars = (unsigned long long*)(smem_raw + 2048);
    float* buf = (float*)(smem_raw + 4096);

    const int tid  = threadIdx.x;
    const int lane = tid & 31;
    const int warp = tid >> 5;
    const unsigned int mbar0 = smem_u32(mbars);

    for (int i = tid; i < DDIM; i += TPB) sv[i] = v[i];
    if (tid == 0) {
#pragma unroll
        for (int s = 0; s < STAGES; s++) mbar_init(mbar0 + 8 * s, 1);
    }
    __syncthreads();

    // v slice in registers for the whole matvec (1 block/SM -> regs cheap)
    const float4* vv4 = (const float4*)sv;
    const float4 y0 = vv4[lane +  0];
    const float4 y1 = vv4[lane + 32];
    const float4 y2 = vv4[lane + 64];
    const float4 y3 = vv4[lane + 96];

    const int ntiles  = (N + TILE_ROWS - 1) / TILE_ROWS;
    const int mytiles = (ntiles - blockIdx.x + gridDim.x - 1) / gridDim.x;

    // issue tile k (global tile bid + k*grid) into stage k%STAGES  (thread 0 only)
    auto issue_tile = [&](int k) {
        if (k < mytiles) {
            int t = blockIdx.x + k * gridDim.x;
            int rows = N - t * TILE_ROWS;
            if (rows > TILE_ROWS) rows = TILE_ROWS;
            unsigned int bytes = (unsigned int)rows * (DDIM * 4);
            unsigned int mb = mbar0 + 8 * (k % STAGES);
            unsigned int dst = smem_u32(buf + (k % STAGES) * TILE_FLOATS);
            mbar_expect_tx(mb, bytes);
            tma_bulk_1d(dst, vs + (size_t)t * TILE_FLOATS, bytes, mb);
        }
    };

    if (tid == 0) {
#pragma unroll
        for (int k = 0; k < STAGES; k++) issue_tile(k);
    }

    for (int k = 0; k < mytiles; k++) {
        // every thread waits for tile k's stage to be full
        mbar_wait(mbar0 + 8 * (k % STAGES), (unsigned int)((k / STAGES) & 1));

        int t   = blockIdx.x + k * gridDim.x;
        int row = t * TILE_ROWS + warp;
        if (row < N) {
            const float4* bb = (const float4*)(buf + (k % STAGES) * TILE_FLOATS
                                               + warp * DDIM);
            float4 x0 = bb[lane +  0];
            float4 x1 = bb[lane + 32];
            float4 x2 = bb[lane + 64];
            float4 x3 = bb[lane + 96];
            float a0 = x0.x*y0.x + x0.y*y0.y + x0.z*y0.z + x0.w*y0.w;
            float a1 = x1.x*y1.x + x1.y*y1.y + x1.z*y1.z + x1.w*y1.w;
            float a2 = x2.x*y2.x + x2.y*y2.y + x2.z*y2.z + x2.w*y2.w;
            float a3 = x3.x*y3.x + x3.y*y3.y + x3.z*y3.z + x3.w*y3.w;
            float acc = (a0 + a1) + (a2 + a3);
#pragma unroll
            for (int o = 16; o; o >>= 1) acc += __shfl_xor_sync(0xffffffffu, acc, o);
            if (lane == 0) {
                g_alpha[row] = acc;
                atomicAdd(&g_hist[fkey(acc) >> 16], 1u);
            }
        }
        __syncthreads();          // all warps done with stage k%STAGES
        if (tid == 0) issue_tile(k + STAGES);
    }

    // ---------------- last-block election ------------------------------------
    __shared__ unsigned int s_isLast;
    __threadfence();
    __syncthreads();
    if (tid == 0)
        s_isLast = (atomicAdd(&g_done, 1u) == gridDim.x - 1) ? 1u : 0u;
    __syncthreads();
    if (!s_isLast) return;
    __threadfence();

    // -------- phase 2: coarse sums from fine hist, then threshold bin --------
    __shared__ unsigned int sc[NCHUNK];
    {
        const uint4* h4 = (const uint4*)g_hist;
        unsigned int s = 0;
        int base = tid * 32;                      // 128 bins per thread
#pragma unroll 8
        for (int j = 0; j < 32; j++) {
            uint4 u = h4[base + j];
            s += u.x + u.y + u.z + u.w;
        }
        __shared__ unsigned int half[TPB];
        half[tid] = s;
        __syncthreads();
        if (tid < NCHUNK) sc[tid] = half[2 * tid] + half[2 * tid + 1];
        __syncthreads();
    }

    __shared__ int s_chunk;
    __shared__ unsigned int s_above;
    __shared__ unsigned int s_tb;
    if (tid == 0) {
        unsigned int cum = 0;
        int c;
        for (c = 255; c >= 0; c--) {
            if (cum + sc[c] >= (unsigned int)TOPK) break;
            cum += sc[c];
        }
        if (c < 0) c = 0;
        s_chunk = c;
        s_above = cum;
    }
    __syncthreads();
    __shared__ unsigned int sf[256];
    if (tid < 256) sf[tid] = g_hist[s_chunk * 256 + tid];
    __syncthreads();
    if (tid == 0) {
        unsigned int cum = s_above;
        int b;
        for (b = 255; b >= 0; b--) {
            cum += sf[b];
            if (cum >= (unsigned int)TOPK) break;
        }
        if (b < 0) b = 0;
        s_tb = (unsigned int)(s_chunk * 256 + b);
    }
    __syncthreads();
    unsigned int tb = s_tb;

    // -------- phase 3: scan alpha (L2-hot), candidates into smem -------------
    float* sval = buf;                      // alias tile buffers
    int*   sidx = (int*)(buf + MAXCAND);
    __shared__ int s_cand;
    if (tid == 0) s_cand = 0;
    __syncthreads();

    int n4 = N >> 2;
    for (int i = tid; i < n4; i += TPB) {
        float4 a = ((const float4*)g_alpha)[i];
        int base = i << 2;
        if ((fkey(a.x) >> 16) >= tb) {
            int p = atomicAdd(&s_cand, 1);
            if (p < MAXCAND) { sval[p] = a.x; sidx[p] = base + 0; }
        }
        if ((fkey(a.y) >> 16) >= tb) {
            int p = atomicAdd(&s_cand, 1);
            if (p < MAXCAND) { sval[p] = a.y; sidx[p] = base + 1; }
        }
        if ((fkey(a.z) >> 16) >= tb) {
            int p = atomicAdd(&s_cand, 1);
            if (p < MAXCAND) { sval[p] = a.z; sidx[p] = base + 2; }
        }
        if ((fkey(a.w) >> 16) >= tb) {
            int p = atomicAdd(&s_cand, 1);
            if (p < MAXCAND) { sval[p] = a.w; sidx[p] = base + 3; }
        }
    }
    if (tid == 0) {
        for (int i = n4 << 2; i < N; i++) {
            float a = g_alpha[i];
            if ((fkey(a) >> 16) >= tb) {
                int p = atomicAdd(&s_cand, 1);
                if (p < MAXCAND) { sval[p] = a; sidx[p] = i; }
            }
        }
    }
    __syncthreads();
    int C = s_cand;
    if (C > MAXCAND) C = MAXCAND;

    // -------- phase 4: max, rank-select, softmax, weighted sum ---------------
    __shared__ float r1[TPB];
    __shared__ float r2[TPB];

    float m = -INFINITY;
    for (int i = tid; i < C; i += TPB) m = fmaxf(m, sval[i]);
    r1[tid] = m;
    __syncthreads();
    for (int s = TPB / 2; s; s >>= 1) {
        if (tid < s) r1[tid] = fmaxf(r1[tid], r1[tid + s]);
        __syncthreads();
    }
    m = r1[0];
    __syncthreads();

    float se = 0.f, acc = 0.f;
    for (int i = tid; i < C; i += TPB) {
        float vi = sval[i];
        unsigned int ki = fkey(vi);
        int rank = 0;
        for (int j = 0; j < C; j++) {
            unsigned int kj = fkey(sval[j]);
            rank += (kj > ki) || (kj == ki && j < i);
        }
        if (rank < TOPK) {
            float e = __expf(vi - m);
            se += e;
            acc += e * scores[sidx[i]];
        }
    }
    r1[tid] = se;
    r2[tid] = acc;
    __syncthreads();
    for (int s = TPB / 2; s; s >>= 1) {
        if (tid < s) {
            r1[tid] += r1[tid + s];
            r2[tid] += r2[tid + s];
        }
        __syncthreads();
    }
    if (tid == 0) out[0] = r2[0] / r1[0];

    // -------- phase 5: selective reset for next graph replay -----------------
    if (tid < NCHUNK) {
        if (sc[tid] != 0u) {
            uint4 z = make_uint4(0u, 0u, 0u, 0u);
            uint4* dst = (uint4*)&g_hist[tid * 256];
#pragma unroll
            for (int j = 0; j < 64; j++) dst[j] = z;
        }
    }
    if (tid == 0) g_done = 0u;
}

// ---------------- launch ------------------------------------------------------
extern "C" void kernel_launch(void* const* d_in, const int* in_sizes, int n_in,
                              void* d_out, int out_size) {
    const float* v      = (const float*)d_in[0];
    const float* vs     = (const float*)d_in[1];
    const float* scores = (const float*)d_in[2];
    float* out = (float*)d_out;
    int N = in_sizes[2];
    (void)n_in; (void)out_size;

    cudaFuncSetAttribute(fused_kernel,
                         cudaFuncAttributeMaxDynamicSharedMemorySize, SMEM_BYTES);
    fused_kernel<<<NBLOCKS, TPB, SMEM_BYTES>>>(v, vs, scores, out, N);
}